// round 9
// baseline (speedup 1.0000x reference)
#include <cuda_runtime.h>
#include <cuda_fp16.h>
#include <cstdint>

// FwFM second-order via mma.sync fp16 + cp.async double-buffered pipeline.
//   out[c] = sum_l x[l,c] * T[l,c],  T = L^T-GEMM:  A = X^T (M=cols), B = L^T.
// X staged fp32 in smem [k][col] via LDGSTS (no reg staging); fragments built
// from fp32 smem with cvt at use; epilogue x read in fp32.

#define KF 39
#define BD (8192 * 64)
#define NCOL 128            // columns per tile
#define THREADS 256         // 8 warps x 16 cols
#define TILES 4             // tiles per CTA
#define PITCH 132           // floats per k-row: 132%32=4 (conflict-free), 132*4B=33*16B (LDGSTS-aligned)
#define KROWS 48
#define BUFF (KROWS * PITCH)   // floats per buffer
#define NTILE 9

typedef unsigned int u32;

// Precomputed B fragments: [tile][lane][2] u32 (b0,b1 of m16n8k16 col-major f16 B-frag)
__device__ u32 Bfrag_g[NTILE * 32 * 2];

__constant__ int c_kt[NTILE] = {0, 0, 0, 0, 0, 1, 1, 1, 2};
__constant__ int c_nt[NTILE] = {0, 1, 2, 3, 4, 2, 3, 4, 4};

__global__ void fwfm_prep(const float* __restrict__ W) {
    int t = threadIdx.x;
    if (t >= NTILE * 32) return;
    int tile = t >> 5, lane = t & 31;
    int g = lane >> 2, tq = lane & 3;
    int kt = c_kt[tile], nt = c_nt[tile];
    int l = nt * 8 + g;
    int k0 = kt * 16 + 2 * tq;
    float v[4];
#pragma unroll
    for (int d = 0; d < 4; ++d) {
        int k = k0 + (d >> 1) * 8 + (d & 1);
        v[d] = (l < KF && k < l) ? 0.5f * (W[k * KF + l] + W[l * KF + k]) : 0.0f;
    }
    __half2 b0 = __floats2half2_rn(v[0], v[1]);
    __half2 b1 = __floats2half2_rn(v[2], v[3]);
    Bfrag_g[(tile * 32 + lane) * 2 + 0] = *(u32*)&b0;
    Bfrag_g[(tile * 32 + lane) * 2 + 1] = *(u32*)&b1;
}

static __device__ __forceinline__ void mma_f16(float* d, const u32* a, u32 b0, u32 b1) {
    asm volatile(
        "mma.sync.aligned.m16n8k16.row.col.f32.f16.f16.f32 "
        "{%0,%1,%2,%3}, {%4,%5,%6,%7}, {%8,%9}, {%0,%1,%2,%3};"
        : "+f"(d[0]), "+f"(d[1]), "+f"(d[2]), "+f"(d[3])
        : "r"(a[0]), "r"(a[1]), "r"(a[2]), "r"(a[3]), "r"(b0), "r"(b1));
}

static __device__ __forceinline__ u32 smem_u32(const void* p) {
    u32 a;
    asm("{ .reg .u64 t; cvta.to.shared.u64 t, %1; cvt.u32.u64 %0, t; }" : "=r"(a) : "l"(p));
    return a;
}
static __device__ __forceinline__ void cp16(u32 s, const void* g) {
    asm volatile("cp.async.cg.shared.global [%0], [%1], 16;" :: "r"(s), "l"(g) : "memory");
}
static __device__ __forceinline__ u32 packh2(float a, float b) {
    __half2 h = __floats2half2_rn(a, b);
    return *(u32*)&h;
}

__global__ __launch_bounds__(THREADS, 4)
void fwfm_main(const float* __restrict__ x, float* __restrict__ out) {
    extern __shared__ float Xs[];   // 2 buffers of [KROWS][PITCH] fp32

    const int tid = threadIdx.x;
    const size_t col_base = (size_t)blockIdx.x * (TILES * NCOL);

    // Zero pad rows 39..47 of both buffers once (never overwritten by cp.async).
    for (int i = tid; i < 2 * (KROWS - KF) * PITCH; i += THREADS) {
        int b = i / ((KROWS - KF) * PITCH);
        int r = i - b * ((KROWS - KF) * PITCH);
        Xs[b * BUFF + KF * PITCH + r] = 0.0f;
    }

    // Issue tile 0 loads: 39 rows x 128 floats; 8 rows per sweep (32 lanes x 16B).
    {
        const float* src0 = x + col_base;
        u32 dst0 = smem_u32(Xs);
#pragma unroll
        for (int it = 0; it < 5; ++it) {
            int row = it * 8 + (tid >> 5);
            if (row < KF)
                cp16(dst0 + (u32)(row * PITCH + (tid & 31) * 4) * 4u,
                     src0 + (size_t)row * BD + (tid & 31) * 4);
        }
        asm volatile("cp.async.commit_group;" ::: "memory");
    }

    const int lane = tid & 31;
    const int g = lane >> 2, tq = lane & 3;
    const int cw = (tid >> 5) * 16;           // warp's 16 columns within tile

    // Preload all 9 B fragments (LDG.64, L2-broadcast).
    u32 bf[NTILE][2];
#pragma unroll
    for (int t = 0; t < NTILE; ++t) {
        unsigned long long q = reinterpret_cast<const unsigned long long*>(Bfrag_g)[t * 32 + lane];
        bf[t][0] = (u32)q;
        bf[t][1] = (u32)(q >> 32);
    }

    for (int t = 0; t < TILES; ++t) {
        if (t + 1 < TILES) {
            const float* srcn = x + col_base + (size_t)(t + 1) * NCOL;
            u32 dstn = smem_u32(Xs + ((t + 1) & 1) * BUFF);
#pragma unroll
            for (int it = 0; it < 5; ++it) {
                int row = it * 8 + (tid >> 5);
                if (row < KF)
                    cp16(dstn + (u32)(row * PITCH + (tid & 31) * 4) * 4u,
                         srcn + (size_t)row * BD + (tid & 31) * 4);
            }
            asm volatile("cp.async.commit_group;" ::: "memory");
            asm volatile("cp.async.wait_group 1;" ::: "memory");
        } else {
            asm volatile("cp.async.wait_group 0;" ::: "memory");
        }
        __syncthreads();

        const float* B = Xs + (t & 1) * BUFF;

        float d[5][4];
#pragma unroll
        for (int nt = 0; nt < 5; ++nt)
#pragma unroll
            for (int r = 0; r < 4; ++r) d[nt][r] = 0.0f;

#pragma unroll
        for (int kt = 0; kt < 3; ++kt) {
            // A fragment from fp32 [k][col]: rows k0+2tq(+1,+8,+9), cols cw+g(+8).
            const float* ap = B + (kt * 16 + 2 * tq) * PITCH + cw + g;
            u32 a[4];
            a[0] = packh2(ap[0], ap[PITCH]);
            a[1] = packh2(ap[8], ap[PITCH + 8]);
            a[2] = packh2(ap[8 * PITCH], ap[9 * PITCH]);
            a[3] = packh2(ap[8 * PITCH + 8], ap[9 * PITCH + 8]);
            if (kt == 0) {
#pragma unroll
                for (int q = 0; q < 5; ++q) mma_f16(d[q], a, bf[q][0], bf[q][1]);
            } else if (kt == 1) {
#pragma unroll
                for (int q = 5; q < 8; ++q) mma_f16(d[q - 3], a, bf[q][0], bf[q][1]);
            } else {
                mma_f16(d[4], a, bf[8][0], bf[8][1]);
            }
        }

        // Epilogue: out[c] = sum_l x[l,c]*T[l,c]; x fp32 from smem (conflict-free).
        {
            const float* xg = B + cw + g;       // element l at xg[l*PITCH]
            float sg = 0.0f, sg8 = 0.0f;
#pragma unroll
            for (int nt = 0; nt < 5; ++nt) {
                const int l0 = nt * 8 + 2 * tq;
                sg = fmaf(xg[l0 * PITCH], d[nt][0], sg);
                sg = fmaf(xg[(l0 + 1) * PITCH], d[nt][1], sg);
                sg8 = fmaf(xg[l0 * PITCH + 8], d[nt][2], sg8);
                sg8 = fmaf(xg[(l0 + 1) * PITCH + 8], d[nt][3], sg8);
            }
            sg += __shfl_xor_sync(0xFFFFFFFFu, sg, 1);
            sg += __shfl_xor_sync(0xFFFFFFFFu, sg, 2);
            sg8 += __shfl_xor_sync(0xFFFFFFFFu, sg8, 1);
            sg8 += __shfl_xor_sync(0xFFFFFFFFu, sg8, 2);
            if (tq == 0) {
                float* o = out + col_base + (size_t)t * NCOL + cw + g;
                o[0] = sg;
                o[8] = sg8;
            }
        }
        __syncthreads();   // buffer reuse fence (next cp.async overwrites buf[t&1] at t+2)
    }
}

extern "C" void kernel_launch(void* const* d_in, const int* in_sizes, int n_in,
                              void* d_out, int out_size) {
    const float* x = (const float*)d_in[0];   // [39, 8192, 64] fp32
    const float* W = (const float*)d_in[1];   // [39, 39] fp32
    float* out = (float*)d_out;               // [8192, 64] fp32

    static_assert(2 * BUFF * sizeof(float) < 227 * 1024, "smem");
    cudaFuncSetAttribute(fwfm_main, cudaFuncAttributeMaxDynamicSharedMemorySize,
                         2 * BUFF * (int)sizeof(float));

    fwfm_prep<<<1, NTILE * 32>>>(W);
    fwfm_main<<<BD / (TILES * NCOL), THREADS, 2 * BUFF * sizeof(float)>>>(x, out);
}